// round 3
// baseline (speedup 1.0000x reference)
#include <cuda_runtime.h>

// Problem constants (fixed by the dataset): B=4, T=4096, d=64, q=256,
// Ctraj=32, nA=4, L=1024, C=2.  Aset indices t,j are in [0,256).
#define SCALE_INV (1.0f/256.0f)
#define BETA_INV  10.0f

// Scratch (no allocations allowed in kernel_launch)
__device__ float g_Yt[256*32*64];   // [j][c][d]   (2 MB)
__device__ float g_y2[256*32];      // [j][c]
__device__ float g_x2[4*256];       // [b][t]  (only t<256 ever used)
__device__ float g_S [4*4*32*2];    // [b][a][c][{sum e, sum phi*e}]

// ---------------------------------------------------------------------------
// prep: transpose Y, build y2/x2 tables, zero accumulators
// blocks 0..511   : tiled transpose Y(c,d,j) -> Yt(j,c,d)
// blocks 512..543 : y2[j][c] = sum_d Y[c][d][j]^2        (c = bid-512)
// blocks 544..547 : x2[b][t] = sum_d traj[b][t][d]^2     (b = bid-544, t<256)
// block  548      : zero g_S
// ---------------------------------------------------------------------------
__global__ void __launch_bounds__(256) prep_kernel(const float* __restrict__ traj,
                                                   const float* __restrict__ Y) {
    int bid = blockIdx.x, tid = threadIdx.x;
    if (bid < 512) {
        __shared__ float tile[32][33];
        int c  = bid >> 4;
        int rem = bid & 15;
        int dt = (rem >> 3) * 32;      // d tile base (0 or 32)
        int jt = (rem & 7) * 32;       // j tile base
        int tx = tid & 31, ty = tid >> 5;   // 32 x 8
        const float* src = Y + c*16384 + dt*256 + jt;
        #pragma unroll
        for (int r = ty; r < 32; r += 8)
            tile[r][tx] = src[r*256 + tx];          // coalesced over j
        __syncthreads();
        float* dst = g_Yt + jt*2048 + c*64 + dt;
        #pragma unroll
        for (int r = ty; r < 32; r += 8)
            dst[r*2048 + tx] = tile[tx][r];         // coalesced over d
    } else if (bid < 544) {
        int c = bid - 512;
        int j = tid;                                  // 256 threads = 256 j's
        const float* src = Y + c*16384 + j;
        float s = 0.f;
        #pragma unroll
        for (int d = 0; d < 64; d++) { float v = src[d*256]; s += v*v; }
        g_y2[j*32 + c] = s;
    } else if (bid < 548) {
        int b = bid - 544;
        int t = tid;
        const float4* src = (const float4*)(traj + (size_t)(b*4096 + t)*64);
        float s = 0.f;
        #pragma unroll
        for (int i = 0; i < 16; i++) {
            float4 v = src[i];
            s += v.x*v.x + v.y*v.y + v.z*v.z + v.w*v.w;
        }
        g_x2[b*256 + t] = s;
    } else {
        for (int i = tid; i < 4*4*32*2; i += 256) g_S[i] = 0.f;
    }
}

// ---------------------------------------------------------------------------
// main: block per (j, b).  Stage Yt[j] (8 KB) in smem, scan this b's Aset in
// chunks of 512 entries, queue matches (j_entry == j), process them
// warp-collectively with lane = c.
// ---------------------------------------------------------------------------
__global__ void __launch_bounds__(128) main_kernel(const float* __restrict__ traj,
                                                   const int2* __restrict__ Aset) {
    const int j = blockIdx.x, b = blockIdx.y;
    const int tid = threadIdx.x, lane = tid & 31, w = tid >> 5;

    __shared__ float4 Ys[16][32];     // Ys[i][c] = Yt[j][c][4i..4i+3]
    __shared__ float  y2s[32];
    __shared__ float4 xw4[4][16];     // per-warp staged traj row
    __shared__ int    qrec[512];      // packed (a<<16)|t
    __shared__ int    qn;
    __shared__ float  Sblk[256];      // [a][c][2]

    const float4* Yt4 = (const float4*)(g_Yt + (size_t)j*2048);
    #pragma unroll
    for (int g = tid; g < 512; g += 128)
        Ys[g & 15][g >> 4] = Yt4[g];
    if (tid < 32) y2s[tid] = g_y2[j*32 + tid];
    for (int i = tid; i < 256; i += 128) Sblk[i] = 0.f;
    __syncthreads();

    const float y2c = y2s[lane];
    float s1[4] = {0.f,0.f,0.f,0.f};
    float s2[4] = {0.f,0.f,0.f,0.f};
    const int2* A2 = Aset + b*4096;

    for (int wave = 0; wave < 8; wave++) {
        if (tid == 0) qn = 0;
        __syncthreads();
        int base = wave * 512;
        #pragma unroll
        for (int k = 0; k < 4; k++) {
            int e = base + k*128 + tid;
            int2 ta = A2[e];                       // (t, j_e)
            if (ta.y == j) {
                int p = atomicAdd(&qn, 1);
                qrec[p] = ta.x | ((e >> 10) << 16);  // a = e / L
            }
        }
        __syncthreads();
        int n = qn;
        for (int m = w; m < n; m += 4) {
            int rec = qrec[m];
            int t = rec & 0xffff, a = rec >> 16;
            const float* xr = traj + (size_t)(b*4096 + t)*64;
            float* xws = (float*)xw4[w];
            xws[lane]      = xr[lane];
            xws[lane + 32] = xr[lane + 32];
            __syncwarp();
            float acc = 0.f;
            #pragma unroll
            for (int i = 0; i < 16; i++) {
                float4 xv = xw4[w][i];
                float4 yv = Ys[i][lane];
                acc += xv.x*yv.x + xv.y*yv.y + xv.z*yv.z + xv.w*yv.w;
            }
            float Dv = g_x2[b*256 + t] + y2c - 2.f*acc;
            float ph = __expf(-Dv * SCALE_INV);
            float ex = __expf(-BETA_INV * ph);
            float pe = ph * ex;
            #pragma unroll
            for (int aa = 0; aa < 4; aa++) {
                if (a == aa) { s1[aa] += ex; s2[aa] += pe; }
            }
            __syncwarp();   // all lanes done reading xw4[w] before next overwrite
        }
        __syncthreads();
    }

    #pragma unroll
    for (int aa = 0; aa < 4; aa++) {
        atomicAdd(&Sblk[aa*64 + lane*2 + 0], s1[aa]);
        atomicAdd(&Sblk[aa*64 + lane*2 + 1], s2[aa]);
    }
    __syncthreads();
    for (int i = tid; i < 256; i += 128)
        atomicAdd(&g_S[b*256 + i], Sblk[i]);
}

// ---------------------------------------------------------------------------
// finalize: odds[b][c] = sum_a S2/(L*S1); out = selu(odds @ W^T + bias)
// 128 threads: warp = b, lane = c
// ---------------------------------------------------------------------------
__global__ void __launch_bounds__(128) final_kernel(const float* __restrict__ W,
                                                    const float* __restrict__ bias,
                                                    float* __restrict__ out) {
    int tid = threadIdx.x;
    int b = tid >> 5, c = tid & 31;
    float odds = 0.f;
    #pragma unroll
    for (int a = 0; a < 4; a++) {
        float v1 = g_S[b*256 + a*64 + c*2 + 0];
        float v2 = g_S[b*256 + a*64 + c*2 + 1];
        odds += v2 / (1024.f * v1);
    }
    float p0 = odds * W[c];
    float p1 = odds * W[32 + c];
    #pragma unroll
    for (int off = 16; off; off >>= 1) {
        p0 += __shfl_xor_sync(0xffffffffu, p0, off);
        p1 += __shfl_xor_sync(0xffffffffu, p1, off);
    }
    if (c == 0) {
        const float sc = 1.0507009873554805f, al = 1.6732632423543772f;
        float x0 = p0 + bias[0];
        float x1 = p1 + bias[1];
        out[b*2 + 0] = (x0 > 0.f) ? sc*x0 : sc*al*expm1f(x0);
        out[b*2 + 1] = (x1 > 0.f) ? sc*x1 : sc*al*expm1f(x1);
    }
}

// ---------------------------------------------------------------------------
extern "C" void kernel_launch(void* const* d_in, const int* in_sizes, int n_in,
                              void* d_out, int out_size) {
    const float* traj = (const float*)d_in[0];   // (4,4096,64)
    const int2*  Aset = (const int2*) d_in[1];   // (4,4,1024,2)
    const float* Y    = (const float*)d_in[2];   // (32,64,256)
    const float* W    = (const float*)d_in[3];   // (2,32)
    const float* bias = (const float*)d_in[4];   // (2,)
    float* out = (float*)d_out;                  // (4,2)

    prep_kernel<<<549, 256>>>(traj, Y);
    dim3 grid(256, 4);
    main_kernel<<<grid, 128>>>(traj, Aset);
    final_kernel<<<1, 128>>>(W, bias, out);
}